// round 12
// baseline (speedup 1.0000x reference)
#include <cuda_runtime.h>
#include <cuda_fp16.h>
#include <cstdint>

#define NB 12
#define DM 128
#define NH 2
#define HD 64
#define NSLICE 4   // 16-component slices per head

struct Consts {              // exactly 368 floats = 92 float4
    float ta[NH];
    float u[NH];
    float bo;
    float pad[3];
    float tb[NH][NB];
    float gam[NH][NB];
    float w[NH][NB];
    float del[NH][NB][NB];
};
#define CONSTS_F4 (sizeof(Consts) / 16)   // 92

__device__ __align__(16) Consts g_cp[NSLICE];

__device__ __forceinline__ __half2 h2ex2(__half2 v) {
    uint32_t a = *reinterpret_cast<uint32_t*>(&v), b;
    asm("ex2.approx.f16x2 %0, %1;" : "=r"(b) : "r"(a));
    return *reinterpret_cast<__half2*>(&b);
}
__device__ __forceinline__ __half2 asH2(uint32_t u) {
    return *reinterpret_cast<__half2*>(&u);
}

// ---------------------------------------------------------------------------
// Setup: ONE node, 8 independent blocks = (head h, 16-comp slice g).
// [round-11 structure, unchanged]
// ---------------------------------------------------------------------------
__global__ void __launch_bounds__(256) spec_setup(
        const float* __restrict__ we, const float* __restrict__ be,
        const float* __restrict__ bp,
        const float* __restrict__ Wq, const float* __restrict__ bq,
        const float* __restrict__ Wk, const float* __restrict__ bk,
        const float* __restrict__ Wv, const float* __restrict__ bv,
        const float* __restrict__ Wo, const float* __restrict__ bo) {
    __shared__ float4 sW4[32 * 33];
    __shared__ float4 sE4[13][32];
    __shared__ float  sC[32][13];
    __shared__ float4 sVPw[8][32];
    __shared__ float  sVP[DM];

    const int tid = threadIdx.x;
    const int h = blockIdx.x >> 2;
    const int g = blockIdx.x & 3;
    const int ibase = h * HD + g * 16;

    for (int idx = tid; idx < 13 * 32; idx += 256) {
        int e = idx >> 5, c = idx & 31;
        float4 v;
        if (e == 0) {
            v = ((const float4*)we)[c];
        } else {
            float4 b4 = ((const float4*)be)[c];
            float4 p4 = ((const float4*)bp)[(e - 1) * 32 + c];
            v = make_float4(b4.x + p4.x, b4.y + p4.y, b4.z + p4.z, b4.w + p4.w);
        }
        sE4[e][c] = v;
    }
    for (int idx = tid; idx < 32 * 32; idx += 256) {
        int r = idx >> 5, c = idx & 31;
        const float* W = (r < 16) ? Wq : Wk;
        int i = ibase + (r & 15);
        sW4[r * 33 + c] = ((const float4*)(W + i * DM))[c];
    }
    {
        int wid = tid >> 5, lane = tid & 31;
        float4 p = make_float4(0.f, 0.f, 0.f, 0.f);
        #pragma unroll
        for (int k = 0; k < 2; k++) {
            int i = ibase + wid * 2 + k;
            float wo = Wo[i];
            float4 v4 = ((const float4*)(Wv + i * DM))[lane];
            p.x = fmaf(wo, v4.x, p.x);
            p.y = fmaf(wo, v4.y, p.y);
            p.z = fmaf(wo, v4.z, p.z);
            p.w = fmaf(wo, v4.w, p.w);
        }
        sVPw[wid][lane] = p;
    }
    __syncthreads();

    if (tid < 32) {
        float4 s = make_float4(0.f, 0.f, 0.f, 0.f);
        #pragma unroll
        for (int w = 0; w < 8; w++) {
            float4 p = sVPw[w][tid];
            s.x += p.x; s.y += p.y; s.z += p.z; s.w += p.w;
        }
        ((float4*)sVP)[tid] = s;
    }

    for (int idx = tid; idx < 32 * 13; idx += 256) {
        int r = idx & 31;
        int e = idx >> 5;
        float a0 = 0.f, a1 = 0.f, a2 = 0.f, a3 = 0.f;
        #pragma unroll
        for (int c = 0; c < 32; c += 4) {
            float4 w0 = sW4[r * 33 + c],     e0 = sE4[e][c];
            float4 w1 = sW4[r * 33 + c + 1], e1 = sE4[e][c + 1];
            float4 w2 = sW4[r * 33 + c + 2], e2 = sE4[e][c + 2];
            float4 w3 = sW4[r * 33 + c + 3], e3 = sE4[e][c + 3];
            a0 = fmaf(w0.x, e0.x, fmaf(w0.y, e0.y, fmaf(w0.z, e0.z, fmaf(w0.w, e0.w, a0))));
            a1 = fmaf(w1.x, e1.x, fmaf(w1.y, e1.y, fmaf(w1.z, e1.z, fmaf(w1.w, e1.w, a1))));
            a2 = fmaf(w2.x, e2.x, fmaf(w2.y, e2.y, fmaf(w2.z, e2.z, fmaf(w2.w, e2.w, a2))));
            a3 = fmaf(w3.x, e3.x, fmaf(w3.y, e3.y, fmaf(w3.z, e3.z, fmaf(w3.w, e3.w, a3))));
        }
        float acc = (a0 + a1) + (a2 + a3);
        if (e > 0) acc += (r < 16) ? bq[ibase + r] : bk[ibase + r - 16];
        sC[r][e] = acc;
    }
    __syncthreads();

    const float cfac = 0.125f * 1.4426950408889634f;

    if (tid < 182) {
        int rr = tid;
        if (rr == 1 || (rr >= 26 && rr < 38)) {
            int e = (rr == 1) ? 0 : (rr - 26 + 1);
            const float4* A = (const float4*)sVP;
            float a0 = 0.f, a1 = 0.f, a2 = 0.f, a3 = 0.f;
            #pragma unroll
            for (int c = 0; c < 32; c += 4) {
                float4 v0 = A[c],     e0 = sE4[e][c];
                float4 v1 = A[c + 1], e1 = sE4[e][c + 1];
                float4 v2 = A[c + 2], e2 = sE4[e][c + 2];
                float4 v3 = A[c + 3], e3 = sE4[e][c + 3];
                a0 = fmaf(v0.x, e0.x, fmaf(v0.y, e0.y, fmaf(v0.z, e0.z, fmaf(v0.w, e0.w, a0))));
                a1 = fmaf(v1.x, e1.x, fmaf(v1.y, e1.y, fmaf(v1.z, e1.z, fmaf(v1.w, e1.w, a1))));
                a2 = fmaf(v2.x, e2.x, fmaf(v2.y, e2.y, fmaf(v2.z, e2.z, fmaf(v2.w, e2.w, a2))));
                a3 = fmaf(v3.x, e3.x, fmaf(v3.y, e3.y, fmaf(v3.z, e3.z, fmaf(v3.w, e3.w, a3))));
            }
            float acc = (a0 + a1) + (a2 + a3);
            if (rr == 1) {
                g_cp[g].u[h] = acc;
            } else {
                float bw = 0.f;
                #pragma unroll
                for (int il = 0; il < 16; il++)
                    bw = fmaf(bv[ibase + il], Wo[ibase + il], bw);
                g_cp[g].w[h][rr - 26] = acc + bw;
            }
        } else {
            const float* A;
            const float* B;
            float* dst;
            if (rr == 0)      { A = &sC[0][0];  B = &sC[16][0]; dst = &g_cp[g].ta[h]; }
            else if (rr < 14) { int b = rr - 2;
                                A = &sC[0][0];  B = &sC[16][1 + b]; dst = &g_cp[g].tb[h][b]; }
            else if (rr < 26) { int b = rr - 14;
                                A = &sC[0][1 + b]; B = &sC[16][0]; dst = &g_cp[g].gam[h][b]; }
            else              { int idx = rr - 38, q = idx / NB, k = idx % NB;
                                A = &sC[0][1 + q]; B = &sC[16][1 + k]; dst = &g_cp[g].del[h][q][k]; }
            float a0 = 0.f, a1 = 0.f;
            #pragma unroll
            for (int il = 0; il < 16; il += 2) {
                a0 = fmaf(A[il * 13],       B[il * 13],       a0);
                a1 = fmaf(A[(il + 1) * 13], B[(il + 1) * 13], a1);
            }
            *dst = (a0 + a1) * cfac;
        }
    }
    if (h == 0 && tid == 182) g_cp[g].bo = (g == 0) ? bo[0] : 0.f;
    // zero pad/bo fields in non-owner slices so the blind sum is exact
    if (h == 0 && tid >= 183 && tid < 186) {
        ((float*)&g_cp[g])[5 + (tid - 183)] = 0.f;   // pad[0..2]
    }
}

// ---------------------------------------------------------------------------
// Main kernel: 2 threads/token (one per head), fp16x2 over k-pairs.
// Prologue: COALESCED float4 staging of the 4 partial structs into smem
// (92 float4 per struct), summed in fp32, then converted to half2 tables
// entirely from smem. No scattered global loads.
// ---------------------------------------------------------------------------
__global__ void __launch_bounds__(256, 4) spec_main(const float* __restrict__ x,
                                                    float* __restrict__ out, int N2) {
    __shared__ __align__(16) float sRaw[CONSTS_F4 * 4];   // summed Consts (fp32)
    __shared__ __align__(16) __half2 sDel[NH][NB][8];
    __shared__ __half2 sTb[NH][6], sW[NH][6];
    __shared__ __half2 sGam[NH][NB];
    __shared__ __half2 sTa[NH], sU[NH];
    __shared__ float sBo;

    {
        int td = threadIdx.x;
        // coalesced partial-sum staging: 92 float4 rows
        if (td < CONSTS_F4) {
            const float4* p0 = (const float4*)&g_cp[0];
            const float4* p1 = (const float4*)&g_cp[1];
            const float4* p2 = (const float4*)&g_cp[2];
            const float4* p3 = (const float4*)&g_cp[3];
            float4 a = p0[td], b = p1[td], c = p2[td], d = p3[td];
            float4 s = make_float4((a.x + b.x) + (c.x + d.x),
                                   (a.y + b.y) + (c.y + d.y),
                                   (a.z + b.z) + (c.z + d.z),
                                   (a.w + b.w) + (c.w + d.w));
            ((float4*)sRaw)[td] = s;
        }
        __syncthreads();

        const Consts* C = (const Consts*)sRaw;
        for (int i = td; i < NH * NB * 6; i += 256) {
            int hh = i / (NB * 6);
            int r = i % (NB * 6);
            int q = r / 6, j = r % 6;
            sDel[hh][q][j] = __floats2half2_rn(C->del[hh][q][2 * j],
                                               C->del[hh][q][2 * j + 1]);
        }
        if (td < NH * 6) {
            int hh = td / 6, j = td % 6;
            sTb[hh][j] = __floats2half2_rn(C->tb[hh][2 * j], C->tb[hh][2 * j + 1]);
            sW[hh][j]  = __floats2half2_rn(C->w[hh][2 * j],  C->w[hh][2 * j + 1]);
        }
        if (td < NH * NB) {
            int hh = td / NB, q = td % NB;
            float gm = C->gam[hh][q];
            sGam[hh][q] = __floats2half2_rn(gm, gm);
        }
        if (td < NH) {
            sTa[td] = __floats2half2_rn(C->ta[td], C->ta[td]);
            sU[td]  = __floats2half2_rn(C->u[td],  C->u[td]);
        }
        if (td == 0) sBo = C->bo;
    }
    __syncthreads();

    int t = blockIdx.x * blockDim.x + threadIdx.x;
    if (t >= N2) return;
    int n = t >> 1;
    int h = t & 1;

    __half2 x2[6];
    {
        const float4* xp = (const float4*)(x + (size_t)n * NB);
        float4 a0 = xp[0], a1 = xp[1], a2 = xp[2];
        x2[0] = __floats2half2_rn(a0.x, a0.y);
        x2[1] = __floats2half2_rn(a0.z, a0.w);
        x2[2] = __floats2half2_rn(a1.x, a1.y);
        x2[3] = __floats2half2_rn(a1.z, a1.w);
        x2[4] = __floats2half2_rn(a2.x, a2.y);
        x2[5] = __floats2half2_rn(a2.z, a2.w);
    }

    __half2 ah2 = sTa[h], uh2 = sU[h];
    __half2 t2[6], m2[6];
    #pragma unroll
    for (int j = 0; j < 6; j++) {
        t2[j] = __hfma2(x2[j], ah2, sTb[h][j]);
        m2[j] = __hfma2(x2[j], uh2, sW[h][j]);
    }

    float contrib[NB];
    #pragma unroll
    for (int q = 0; q < NB; q++) {
        __half2 gq2 = sGam[h][q];
        __half2 xq = ((q & 1) == 0) ? __low2half2(x2[q >> 1])
                                    : __high2half2(x2[q >> 1]);
        const uint4* dp = (const uint4*)&sDel[h][q][0];
        uint4 dA = dp[0];
        uint2 dB = ((const uint2*)dp)[2];

        __half2 z = __floats2half2_rn(0.f, 0.f);
        __half2 rsA = z, rsB = z, dsA = z, dsB = z;

        __half2 s0 = __hfma2(xq, t2[0], __hfma2(x2[0], gq2, asH2(dA.x)));
        __half2 s3 = __hfma2(xq, t2[3], __hfma2(x2[3], gq2, asH2(dA.w)));
        __half2 e0 = h2ex2(s0);
        __half2 e3 = h2ex2(s3);
        rsA = __hadd2(rsA, e0);  dsA = __hfma2(e0, m2[0], dsA);
        rsB = __hadd2(rsB, e3);  dsB = __hfma2(e3, m2[3], dsB);

        __half2 s1 = __hfma2(xq, t2[1], __hfma2(x2[1], gq2, asH2(dA.y)));
        __half2 s4 = __hfma2(xq, t2[4], __hfma2(x2[4], gq2, asH2(dB.x)));
        __half2 e1 = h2ex2(s1);
        __half2 e4 = h2ex2(s4);
        rsA = __hadd2(rsA, e1);  dsA = __hfma2(e1, m2[1], dsA);
        rsB = __hadd2(rsB, e4);  dsB = __hfma2(e4, m2[4], dsB);

        __half2 s2 = __hfma2(xq, t2[2], __hfma2(x2[2], gq2, asH2(dA.z)));
        __half2 s5 = __hfma2(xq, t2[5], __hfma2(x2[5], gq2, asH2(dB.y)));
        __half2 e2 = h2ex2(s2);
        __half2 e5 = h2ex2(s5);
        rsA = __hadd2(rsA, e2);  dsA = __hfma2(e2, m2[2], dsA);
        rsB = __hadd2(rsB, e5);  dsB = __hfma2(e5, m2[5], dsB);

        __half2 rs2 = __hadd2(rsA, rsB);
        __half2 ds2 = __hadd2(dsA, dsB);
        float2 rf = __half22float2(rs2);
        float2 df = __half22float2(ds2);
        contrib[q] = __fdividef(df.x + df.y, rf.x + rf.y);
    }

    #pragma unroll
    for (int q = 0; q < NB; q++)
        contrib[q] += __shfl_xor_sync(0xffffffffu, contrib[q], 1);

    if (h == 0) {
        float b = sBo;
        const float4* xp = (const float4*)(x + (size_t)n * NB);
        float4 a0 = xp[0], a1 = xp[1], a2 = xp[2];
        float4 o0 = make_float4(a0.x + contrib[0] + b,  a0.y + contrib[1] + b,
                                a0.z + contrib[2] + b,  a0.w + contrib[3] + b);
        float4 o1 = make_float4(a1.x + contrib[4] + b,  a1.y + contrib[5] + b,
                                a1.z + contrib[6] + b,  a1.w + contrib[7] + b);
        float4 o2 = make_float4(a2.x + contrib[8] + b,  a2.y + contrib[9] + b,
                                a2.z + contrib[10] + b, a2.w + contrib[11] + b);
        float4* op = (float4*)(out + (size_t)n * NB);
        op[0] = o0; op[1] = o1; op[2] = o2;
    }
}

// ---------------------------------------------------------------------------
extern "C" void kernel_launch(void* const* d_in, const int* in_sizes, int n_in,
                              void* d_out, int out_size) {
    const float* x  = (const float*)d_in[0];
    const float* we = (const float*)d_in[1];
    const float* be = (const float*)d_in[2];
    const float* bp = (const float*)d_in[3];
    const float* Wq = (const float*)d_in[4];
    const float* bq = (const float*)d_in[5];
    const float* Wk = (const float*)d_in[6];
    const float* bk = (const float*)d_in[7];
    const float* Wv = (const float*)d_in[8];
    const float* bv = (const float*)d_in[9];
    const float* Wo = (const float*)d_in[10];
    const float* bo = (const float*)d_in[11];
    float* out = (float*)d_out;

    int N = in_sizes[0] / NB;   // 65536 tokens
    int N2 = 2 * N;

    spec_setup<<<NH * NSLICE, 256>>>(we, be, bp, Wq, bq, Wk, bk, Wv, bv, Wo, bo);
    spec_main<<<(N2 + 255) / 256, 256>>>(x, out, N2);
}

// round 13
// speedup vs baseline: 1.1335x; 1.1335x over previous
#include <cuda_runtime.h>
#include <cuda_fp16.h>
#include <cstdint>

#define NB 12
#define DM 128
#define NH 2
#define HD 64

struct Consts {
    float ta[NH];
    float u[NH];
    float bo;
    float pad[3];
    float tb[NH][NB];
    float gam[NH][NB];
    float w[NH][NB];
    float del[NH][NB][NB];
};

__device__ __align__(16) Consts g_c;
__device__ float g_av[3][DM];
__device__ float g_cv[3][NB][DM];

__device__ __forceinline__ __half2 h2ex2(__half2 v) {
    uint32_t a = *reinterpret_cast<uint32_t*>(&v), b;
    asm("ex2.approx.f16x2 %0, %1;" : "=r"(b) : "r"(a));
    return *reinterpret_cast<__half2*>(&b);
}
__device__ __forceinline__ float warp_sum(float v) {
    v += __shfl_xor_sync(0xffffffffu, v, 16);
    v += __shfl_xor_sync(0xffffffffu, v, 8);
    v += __shfl_xor_sync(0xffffffffu, v, 4);
    v += __shfl_xor_sync(0xffffffffu, v, 2);
    v += __shfl_xor_sync(0xffffffffu, v, 1);
    return v;
}

// ---------------------------------------------------------------------------
// Setup 1 (ONE-WAVE version): 1248 warps total (156 blocks x 256 thr).
// Each warp computes 4 consecutive dot-128s sharing one E vector:
// 5 independent LDG.128 in flight (MLP=5), 16 FMA, 4 shfl reductions.
// ---------------------------------------------------------------------------
__global__ __launch_bounds__(256) void spec_setup1(
        const float* __restrict__ we, const float* __restrict__ be,
        const float* __restrict__ bp,
        const float* __restrict__ Wq, const float* __restrict__ bq,
        const float* __restrict__ Wk, const float* __restrict__ bk,
        const float* __restrict__ Wv, const float* __restrict__ bv) {
    int gw = (blockIdx.x * blockDim.x + threadIdx.x) >> 5;
    int lane = threadIdx.x & 31;
    if (gw >= 3 * 13 * DM / 4) return;        // 1248 warps
    int d0 = gw * 4;
    int m = d0 / (13 * DM);
    int r = d0 % (13 * DM);
    int v = r >> 7;
    int i = r & 127;                          // i, i+1, i+2, i+3 same (m,v)
    const float* W  = (m == 0) ? Wq : (m == 1) ? Wk : Wv;
    const float* bb = (m == 0) ? bq : (m == 1) ? bk : bv;

    // issue all 5-6 loads up front (independent)
    float4 w0 = ((const float4*)(W + (i + 0) * DM))[lane];
    float4 w1 = ((const float4*)(W + (i + 1) * DM))[lane];
    float4 w2 = ((const float4*)(W + (i + 2) * DM))[lane];
    float4 w3 = ((const float4*)(W + (i + 3) * DM))[lane];
    float4 ev;
    if (v == 0) {
        ev = ((const float4*)we)[lane];
    } else {
        float4 e = ((const float4*)be)[lane];
        float4 p = ((const float4*)(bp + (v - 1) * DM))[lane];
        ev = make_float4(e.x + p.x, e.y + p.y, e.z + p.z, e.w + p.w);
    }

    float p0 = w0.x * ev.x + w0.y * ev.y + w0.z * ev.z + w0.w * ev.w;
    float p1 = w1.x * ev.x + w1.y * ev.y + w1.z * ev.z + w1.w * ev.w;
    float p2 = w2.x * ev.x + w2.y * ev.y + w2.z * ev.z + w2.w * ev.w;
    float p3 = w3.x * ev.x + w3.y * ev.y + w3.z * ev.z + w3.w * ev.w;
    p0 = warp_sum(p0);
    p1 = warp_sum(p1);
    p2 = warp_sum(p2);
    p3 = warp_sum(p3);

    if (lane == 0) {
        if (v == 0) {
            g_av[m][i]     = p0;
            g_av[m][i + 1] = p1;
            g_av[m][i + 2] = p2;
            g_av[m][i + 3] = p3;
        } else {
            float* dst = &g_cv[m][v - 1][i];
            dst[0] = p0 + bb[i];
            dst[1] = p1 + bb[i + 1];
            dst[2] = p2 + bb[i + 2];
            dst[3] = p3 + bb[i + 3];
        }
    }
}

// ---------------------------------------------------------------------------
// Setup 2: one WARP per length-64 dot product (365 warps). [proven]
// ---------------------------------------------------------------------------
__global__ __launch_bounds__(256) void spec_setup2(const float* __restrict__ Wo,
                                                   const float* __restrict__ bo) {
    int gw = (blockIdx.x * blockDim.x + threadIdx.x) >> 5;
    int lane = threadIdx.x & 31;
    const float cfac = 0.125f * 1.4426950408889634f;

    if (gw >= NH * 182) {
        if (gw == NH * 182 && lane == 0) g_c.bo = bo[0];
        return;
    }
    int h = gw / 182;
    int t = gw % 182;
    int off = h * HD;

    const float* a; const float* b; float* dst; float sc = cfac;
    if (t == 0)       { a = &g_av[0][off]; b = &g_av[1][off]; dst = &g_c.ta[h]; }
    else if (t == 1)  { a = &g_av[2][off]; b = Wo + off; dst = &g_c.u[h]; sc = 1.0f; }
    else if (t < 14)  { int bd = t - 2;  a = &g_av[0][off]; b = &g_cv[1][bd][off]; dst = &g_c.tb[h][bd]; }
    else if (t < 26)  { int bd = t - 14; a = &g_cv[0][bd][off]; b = &g_av[1][off]; dst = &g_c.gam[h][bd]; }
    else if (t < 38)  { int bd = t - 26; a = &g_cv[2][bd][off]; b = Wo + off; dst = &g_c.w[h][bd]; sc = 1.0f; }
    else {
        int idx = t - 38, q = idx / NB, k = idx % NB;
        a = &g_cv[0][q][off]; b = &g_cv[1][k][off]; dst = &g_c.del[h][q][k];
    }
    float2 av = ((const float2*)a)[lane];
    float2 bv = ((const float2*)b)[lane];
    float s = warp_sum(av.x * bv.x + av.y * bv.y);
    if (lane == 0) *dst = s * sc;
}

// ---------------------------------------------------------------------------
// Main kernel: round-10 PROVEN core, verbatim. 2 threads/token (one per
// head), fp16x2 over k-pairs, scalar sDel LDS, 4 accumulation chains.
// ---------------------------------------------------------------------------
__global__ void __launch_bounds__(256, 4) spec_main(const float* __restrict__ x,
                                                    float* __restrict__ out, int N2) {
    __shared__ __half2 sDel[NH][NB][8];
    __shared__ __half2 sTb[NH][6], sW[NH][6];
    __shared__ __half2 sGam[NH][NB];
    __shared__ __half2 sTa[NH], sU[NH];
    __shared__ float sBo;

    {
        int td = threadIdx.x;
        for (int i = td; i < NH * NB * 6; i += 256) {
            int hh = i / (NB * 6);
            int r = i % (NB * 6);
            int q = r / 6, j = r % 6;
            sDel[hh][q][j] = __floats2half2_rn(g_c.del[hh][q][2 * j],
                                               g_c.del[hh][q][2 * j + 1]);
        }
        if (td < NH * 6) {
            int hh = td / 6, j = td % 6;
            sTb[hh][j] = __floats2half2_rn(g_c.tb[hh][2 * j], g_c.tb[hh][2 * j + 1]);
            sW[hh][j]  = __floats2half2_rn(g_c.w[hh][2 * j],  g_c.w[hh][2 * j + 1]);
        }
        if (td < NH * NB) {
            int hh = td / NB, q = td % NB;
            float g = g_c.gam[hh][q];
            sGam[hh][q] = __floats2half2_rn(g, g);
        }
        if (td < NH) {
            sTa[td] = __floats2half2_rn(g_c.ta[td], g_c.ta[td]);
            sU[td]  = __floats2half2_rn(g_c.u[td],  g_c.u[td]);
        }
        if (td == 0) sBo = g_c.bo;
    }
    __syncthreads();

    int t = blockIdx.x * blockDim.x + threadIdx.x;
    if (t >= N2) return;
    int n = t >> 1;
    int h = t & 1;

    __half2 x2[6];
    {
        const float4* xp = (const float4*)(x + (size_t)n * NB);
        float4 a0 = xp[0], a1 = xp[1], a2 = xp[2];
        x2[0] = __floats2half2_rn(a0.x, a0.y);
        x2[1] = __floats2half2_rn(a0.z, a0.w);
        x2[2] = __floats2half2_rn(a1.x, a1.y);
        x2[3] = __floats2half2_rn(a1.z, a1.w);
        x2[4] = __floats2half2_rn(a2.x, a2.y);
        x2[5] = __floats2half2_rn(a2.z, a2.w);
    }

    __half2 ah2 = sTa[h], uh2 = sU[h];
    __half2 t2[6], m2[6];
    #pragma unroll
    for (int j = 0; j < 6; j++) {
        t2[j] = __hfma2(x2[j], ah2, sTb[h][j]);
        m2[j] = __hfma2(x2[j], uh2, sW[h][j]);
    }

    float contrib[NB];
    #pragma unroll
    for (int q = 0; q < NB; q++) {
        __half2 gq2 = sGam[h][q];
        __half2 xq = ((q & 1) == 0) ? __low2half2(x2[q >> 1])
                                    : __high2half2(x2[q >> 1]);
        __half2 z = __floats2half2_rn(0.f, 0.f);
        __half2 rsA = z, rsB = z, dsA = z, dsB = z;
        #pragma unroll
        for (int j = 0; j < 3; j++) {
            __half2 sA = __hfma2(xq, t2[j],     __hfma2(x2[j],     gq2, sDel[h][q][j]));
            __half2 sB = __hfma2(xq, t2[j + 3], __hfma2(x2[j + 3], gq2, sDel[h][q][j + 3]));
            __half2 eA = h2ex2(sA);
            __half2 eB = h2ex2(sB);
            rsA = __hadd2(rsA, eA);
            rsB = __hadd2(rsB, eB);
            dsA = __hfma2(eA, m2[j], dsA);
            dsB = __hfma2(eB, m2[j + 3], dsB);
        }
        __half2 rs2 = __hadd2(rsA, rsB);
        __half2 ds2 = __hadd2(dsA, dsB);
        float2 rf = __half22float2(rs2);
        float2 df = __half22float2(ds2);
        contrib[q] = __fdividef(df.x + df.y, rf.x + rf.y);
    }

    #pragma unroll
    for (int q = 0; q < NB; q++)
        contrib[q] += __shfl_xor_sync(0xffffffffu, contrib[q], 1);

    if (h == 0) {
        float b = sBo;
        const float4* xp = (const float4*)(x + (size_t)n * NB);   // L1/L2 hit
        float4 a0 = xp[0], a1 = xp[1], a2 = xp[2];
        float4 o0 = make_float4(a0.x + contrib[0] + b,  a0.y + contrib[1] + b,
                                a0.z + contrib[2] + b,  a0.w + contrib[3] + b);
        float4 o1 = make_float4(a1.x + contrib[4] + b,  a1.y + contrib[5] + b,
                                a1.z + contrib[6] + b,  a1.w + contrib[7] + b);
        float4 o2 = make_float4(a2.x + contrib[8] + b,  a2.y + contrib[9] + b,
                                a2.z + contrib[10] + b, a2.w + contrib[11] + b);
        float4* op = (float4*)(out + (size_t)n * NB);
        op[0] = o0; op[1] = o1; op[2] = o2;
    }
}

// ---------------------------------------------------------------------------
extern "C" void kernel_launch(void* const* d_in, const int* in_sizes, int n_in,
                              void* d_out, int out_size) {
    const float* x  = (const float*)d_in[0];
    const float* we = (const float*)d_in[1];
    const float* be = (const float*)d_in[2];
    const float* bp = (const float*)d_in[3];
    const float* Wq = (const float*)d_in[4];
    const float* bq = (const float*)d_in[5];
    const float* Wk = (const float*)d_in[6];
    const float* bk = (const float*)d_in[7];
    const float* Wv = (const float*)d_in[8];
    const float* bv = (const float*)d_in[9];
    const float* Wo = (const float*)d_in[10];
    const float* bo = (const float*)d_in[11];
    float* out = (float*)d_out;

    int N = in_sizes[0] / NB;   // 65536 tokens
    int N2 = 2 * N;

    // 1248 warps as ONE wave: 156 blocks x 256 threads
    spec_setup1<<<156, 256>>>(we, be, bp, Wq, bq, Wk, bk, Wv, bv);

    int s2_warps = NH * 182 + 1;                // 365 warps
    spec_setup2<<<(s2_warps + 7) / 8, 256>>>(Wo, bo);

    spec_main<<<(N2 + 255) / 256, 256>>>(x, out, N2);
}

// round 14
// speedup vs baseline: 1.1530x; 1.0172x over previous
#include <cuda_runtime.h>
#include <cuda_fp16.h>
#include <cstdint>

#define NB 12
#define DM 128
#define NH 2
#define HD 64
#define NSLICE 4   // 16-component slices per head

struct Consts {              // exactly 368 floats = 92 float4
    float ta[NH];
    float u[NH];
    float bo;
    float pad[3];
    float tb[NH][NB];
    float gam[NH][NB];
    float w[NH][NB];
    float del[NH][NB][NB];
};
#define CONSTS_F4 (sizeof(Consts) / 16)   // 92

__device__ __align__(16) Consts g_cp[NSLICE];

__device__ __forceinline__ __half2 h2ex2(__half2 v) {
    uint32_t a = *reinterpret_cast<uint32_t*>(&v), b;
    asm("ex2.approx.f16x2 %0, %1;" : "=r"(b) : "r"(a));
    return *reinterpret_cast<__half2*>(&b);
}

// ---------------------------------------------------------------------------
// Setup: ONE node, 8 independent blocks = (head h, 16-comp slice g).
// [round-11 structure — measured ~2us including node gaps]
// ---------------------------------------------------------------------------
__global__ void __launch_bounds__(256) spec_setup(
        const float* __restrict__ we, const float* __restrict__ be,
        const float* __restrict__ bp,
        const float* __restrict__ Wq, const float* __restrict__ bq,
        const float* __restrict__ Wk, const float* __restrict__ bk,
        const float* __restrict__ Wv, const float* __restrict__ bv,
        const float* __restrict__ Wo, const float* __restrict__ bo) {
    __shared__ float4 sW4[32 * 33];
    __shared__ float4 sE4[13][32];
    __shared__ float  sC[32][13];
    __shared__ float4 sVPw[8][32];
    __shared__ float  sVP[DM];

    const int tid = threadIdx.x;
    const int h = blockIdx.x >> 2;
    const int g = blockIdx.x & 3;
    const int ibase = h * HD + g * 16;

    for (int idx = tid; idx < 13 * 32; idx += 256) {
        int e = idx >> 5, c = idx & 31;
        float4 v;
        if (e == 0) {
            v = ((const float4*)we)[c];
        } else {
            float4 b4 = ((const float4*)be)[c];
            float4 p4 = ((const float4*)bp)[(e - 1) * 32 + c];
            v = make_float4(b4.x + p4.x, b4.y + p4.y, b4.z + p4.z, b4.w + p4.w);
        }
        sE4[e][c] = v;
    }
    for (int idx = tid; idx < 32 * 32; idx += 256) {
        int r = idx >> 5, c = idx & 31;
        const float* W = (r < 16) ? Wq : Wk;
        int i = ibase + (r & 15);
        sW4[r * 33 + c] = ((const float4*)(W + i * DM))[c];
    }
    {
        int wid = tid >> 5, lane = tid & 31;
        float4 p = make_float4(0.f, 0.f, 0.f, 0.f);
        #pragma unroll
        for (int k = 0; k < 2; k++) {
            int i = ibase + wid * 2 + k;
            float wo = Wo[i];
            float4 v4 = ((const float4*)(Wv + i * DM))[lane];
            p.x = fmaf(wo, v4.x, p.x);
            p.y = fmaf(wo, v4.y, p.y);
            p.z = fmaf(wo, v4.z, p.z);
            p.w = fmaf(wo, v4.w, p.w);
        }
        sVPw[wid][lane] = p;
    }
    __syncthreads();

    if (tid < 32) {
        float4 s = make_float4(0.f, 0.f, 0.f, 0.f);
        #pragma unroll
        for (int w = 0; w < 8; w++) {
            float4 p = sVPw[w][tid];
            s.x += p.x; s.y += p.y; s.z += p.z; s.w += p.w;
        }
        ((float4*)sVP)[tid] = s;
    }

    for (int idx = tid; idx < 32 * 13; idx += 256) {
        int r = idx & 31;
        int e = idx >> 5;
        float a0 = 0.f, a1 = 0.f, a2 = 0.f, a3 = 0.f;
        #pragma unroll
        for (int c = 0; c < 32; c += 4) {
            float4 w0 = sW4[r * 33 + c],     e0 = sE4[e][c];
            float4 w1 = sW4[r * 33 + c + 1], e1 = sE4[e][c + 1];
            float4 w2 = sW4[r * 33 + c + 2], e2 = sE4[e][c + 2];
            float4 w3 = sW4[r * 33 + c + 3], e3 = sE4[e][c + 3];
            a0 = fmaf(w0.x, e0.x, fmaf(w0.y, e0.y, fmaf(w0.z, e0.z, fmaf(w0.w, e0.w, a0))));
            a1 = fmaf(w1.x, e1.x, fmaf(w1.y, e1.y, fmaf(w1.z, e1.z, fmaf(w1.w, e1.w, a1))));
            a2 = fmaf(w2.x, e2.x, fmaf(w2.y, e2.y, fmaf(w2.z, e2.z, fmaf(w2.w, e2.w, a2))));
            a3 = fmaf(w3.x, e3.x, fmaf(w3.y, e3.y, fmaf(w3.z, e3.z, fmaf(w3.w, e3.w, a3))));
        }
        float acc = (a0 + a1) + (a2 + a3);
        if (e > 0) acc += (r < 16) ? bq[ibase + r] : bk[ibase + r - 16];
        sC[r][e] = acc;
    }
    __syncthreads();

    const float cfac = 0.125f * 1.4426950408889634f;

    if (tid < 182) {
        int rr = tid;
        if (rr == 1 || (rr >= 26 && rr < 38)) {
            int e = (rr == 1) ? 0 : (rr - 26 + 1);
            const float4* A = (const float4*)sVP;
            float a0 = 0.f, a1 = 0.f, a2 = 0.f, a3 = 0.f;
            #pragma unroll
            for (int c = 0; c < 32; c += 4) {
                float4 v0 = A[c],     e0 = sE4[e][c];
                float4 v1 = A[c + 1], e1 = sE4[e][c + 1];
                float4 v2 = A[c + 2], e2 = sE4[e][c + 2];
                float4 v3 = A[c + 3], e3 = sE4[e][c + 3];
                a0 = fmaf(v0.x, e0.x, fmaf(v0.y, e0.y, fmaf(v0.z, e0.z, fmaf(v0.w, e0.w, a0))));
                a1 = fmaf(v1.x, e1.x, fmaf(v1.y, e1.y, fmaf(v1.z, e1.z, fmaf(v1.w, e1.w, a1))));
                a2 = fmaf(v2.x, e2.x, fmaf(v2.y, e2.y, fmaf(v2.z, e2.z, fmaf(v2.w, e2.w, a2))));
                a3 = fmaf(v3.x, e3.x, fmaf(v3.y, e3.y, fmaf(v3.z, e3.z, fmaf(v3.w, e3.w, a3))));
            }
            float acc = (a0 + a1) + (a2 + a3);
            if (rr == 1) {
                g_cp[g].u[h] = acc;
            } else {
                float bw = 0.f;
                #pragma unroll
                for (int il = 0; il < 16; il++)
                    bw = fmaf(bv[ibase + il], Wo[ibase + il], bw);
                g_cp[g].w[h][rr - 26] = acc + bw;
            }
        } else {
            const float* A;
            const float* B;
            float* dst;
            if (rr == 0)      { A = &sC[0][0];  B = &sC[16][0]; dst = &g_cp[g].ta[h]; }
            else if (rr < 14) { int b = rr - 2;
                                A = &sC[0][0];  B = &sC[16][1 + b]; dst = &g_cp[g].tb[h][b]; }
            else if (rr < 26) { int b = rr - 14;
                                A = &sC[0][1 + b]; B = &sC[16][0]; dst = &g_cp[g].gam[h][b]; }
            else              { int idx = rr - 38, q = idx / NB, k = idx % NB;
                                A = &sC[0][1 + q]; B = &sC[16][1 + k]; dst = &g_cp[g].del[h][q][k]; }
            float a0 = 0.f, a1 = 0.f;
            #pragma unroll
            for (int il = 0; il < 16; il += 2) {
                a0 = fmaf(A[il * 13],       B[il * 13],       a0);
                a1 = fmaf(A[(il + 1) * 13], B[(il + 1) * 13], a1);
            }
            *dst = (a0 + a1) * cfac;
        }
    }
    if (h == 0 && tid == 182) g_cp[g].bo = (g == 0) ? bo[0] : 0.f;
    if (h == 0 && tid >= 183 && tid < 186)
        ((float*)&g_cp[g])[5 + (tid - 183)] = 0.f;   // zero pad[0..2]
}

// ---------------------------------------------------------------------------
// Main kernel: round-10 PROVEN core verbatim; prologue = coalesced 4-partial
// sum into smem (92 float4 per struct), conversions read from smem.
// ---------------------------------------------------------------------------
__global__ void __launch_bounds__(256, 4) spec_main(const float* __restrict__ x,
                                                    float* __restrict__ out, int N2) {
    __shared__ __align__(16) float sRaw[CONSTS_F4 * 4];
    __shared__ __half2 sDel[NH][NB][8];
    __shared__ __half2 sTb[NH][6], sW[NH][6];
    __shared__ __half2 sGam[NH][NB];
    __shared__ __half2 sTa[NH], sU[NH];
    __shared__ float sBo;

    {
        int td = threadIdx.x;
        if (td < CONSTS_F4) {
            const float4* p0 = (const float4*)&g_cp[0];
            const float4* p1 = (const float4*)&g_cp[1];
            const float4* p2 = (const float4*)&g_cp[2];
            const float4* p3 = (const float4*)&g_cp[3];
            float4 a = p0[td], b = p1[td], c = p2[td], d = p3[td];
            ((float4*)sRaw)[td] = make_float4((a.x + b.x) + (c.x + d.x),
                                              (a.y + b.y) + (c.y + d.y),
                                              (a.z + b.z) + (c.z + d.z),
                                              (a.w + b.w) + (c.w + d.w));
        }
        __syncthreads();

        const Consts* C = (const Consts*)sRaw;
        for (int i = td; i < NH * NB * 6; i += 256) {
            int hh = i / (NB * 6);
            int r = i % (NB * 6);
            int q = r / 6, j = r % 6;
            sDel[hh][q][j] = __floats2half2_rn(C->del[hh][q][2 * j],
                                               C->del[hh][q][2 * j + 1]);
        }
        if (td < NH * 6) {
            int hh = td / 6, j = td % 6;
            sTb[hh][j] = __floats2half2_rn(C->tb[hh][2 * j], C->tb[hh][2 * j + 1]);
            sW[hh][j]  = __floats2half2_rn(C->w[hh][2 * j],  C->w[hh][2 * j + 1]);
        }
        if (td < NH * NB) {
            int hh = td / NB, q = td % NB;
            float gm = C->gam[hh][q];
            sGam[hh][q] = __floats2half2_rn(gm, gm);
        }
        if (td < NH) {
            sTa[td] = __floats2half2_rn(C->ta[td], C->ta[td]);
            sU[td]  = __floats2half2_rn(C->u[td],  C->u[td]);
        }
        if (td == 0) sBo = C->bo;
    }
    __syncthreads();

    int t = blockIdx.x * blockDim.x + threadIdx.x;
    if (t >= N2) return;
    int n = t >> 1;
    int h = t & 1;

    __half2 x2[6];
    {
        const float4* xp = (const float4*)(x + (size_t)n * NB);
        float4 a0 = xp[0], a1 = xp[1], a2 = xp[2];
        x2[0] = __floats2half2_rn(a0.x, a0.y);
        x2[1] = __floats2half2_rn(a0.z, a0.w);
        x2[2] = __floats2half2_rn(a1.x, a1.y);
        x2[3] = __floats2half2_rn(a1.z, a1.w);
        x2[4] = __floats2half2_rn(a2.x, a2.y);
        x2[5] = __floats2half2_rn(a2.z, a2.w);
    }

    __half2 ah2 = sTa[h], uh2 = sU[h];
    __half2 t2[6], m2[6];
    #pragma unroll
    for (int j = 0; j < 6; j++) {
        t2[j] = __hfma2(x2[j], ah2, sTb[h][j]);
        m2[j] = __hfma2(x2[j], uh2, sW[h][j]);
    }

    float contrib[NB];
    #pragma unroll
    for (int q = 0; q < NB; q++) {
        __half2 gq2 = sGam[h][q];
        __half2 xq = ((q & 1) == 0) ? __low2half2(x2[q >> 1])
                                    : __high2half2(x2[q >> 1]);
        __half2 z = __floats2half2_rn(0.f, 0.f);
        __half2 rsA = z, rsB = z, dsA = z, dsB = z;
        #pragma unroll
        for (int j = 0; j < 3; j++) {
            __half2 sA = __hfma2(xq, t2[j],     __hfma2(x2[j],     gq2, sDel[h][q][j]));
            __half2 sB = __hfma2(xq, t2[j + 3], __hfma2(x2[j + 3], gq2, sDel[h][q][j + 3]));
            __half2 eA = h2ex2(sA);
            __half2 eB = h2ex2(sB);
            rsA = __hadd2(rsA, eA);
            rsB = __hadd2(rsB, eB);
            dsA = __hfma2(eA, m2[j], dsA);
            dsB = __hfma2(eB, m2[j + 3], dsB);
        }
        __half2 rs2 = __hadd2(rsA, rsB);
        __half2 ds2 = __hadd2(dsA, dsB);
        float2 rf = __half22float2(rs2);
        float2 df = __half22float2(ds2);
        contrib[q] = __fdividef(df.x + df.y, rf.x + rf.y);
    }

    #pragma unroll
    for (int q = 0; q < NB; q++)
        contrib[q] += __shfl_xor_sync(0xffffffffu, contrib[q], 1);

    if (h == 0) {
        float b = sBo;
        const float4* xp = (const float4*)(x + (size_t)n * NB);
        float4 a0 = xp[0], a1 = xp[1], a2 = xp[2];
        float4 o0 = make_float4(a0.x + contrib[0] + b,  a0.y + contrib[1] + b,
                                a0.z + contrib[2] + b,  a0.w + contrib[3] + b);
        float4 o1 = make_float4(a1.x + contrib[4] + b,  a1.y + contrib[5] + b,
                                a1.z + contrib[6] + b,  a1.w + contrib[7] + b);
        float4 o2 = make_float4(a2.x + contrib[8] + b,  a2.y + contrib[9] + b,
                                a2.z + contrib[10] + b, a2.w + contrib[11] + b);
        float4* op = (float4*)(out + (size_t)n * NB);
        op[0] = o0; op[1] = o1; op[2] = o2;
    }
}

// ---------------------------------------------------------------------------
extern "C" void kernel_launch(void* const* d_in, const int* in_sizes, int n_in,
                              void* d_out, int out_size) {
    const float* x  = (const float*)d_in[0];
    const float* we = (const float*)d_in[1];
    const float* be = (const float*)d_in[2];
    const float* bp = (const float*)d_in[3];
    const float* Wq = (const float*)d_in[4];
    const float* bq = (const float*)d_in[5];
    const float* Wk = (const float*)d_in[6];
    const float* bk = (const float*)d_in[7];
    const float* Wv = (const float*)d_in[8];
    const float* bv = (const float*)d_in[9];
    const float* Wo = (const float*)d_in[10];
    const float* bo = (const float*)d_in[11];
    float* out = (float*)d_out;

    int N = in_sizes[0] / NB;   // 65536 tokens
    int N2 = 2 * N;

    spec_setup<<<NH * NSLICE, 256>>>(we, be, bp, Wq, bq, Wk, bk, Wv, bv, Wo, bo);
    spec_main<<<(N2 + 255) / 256, 256>>>(x, out, N2);
}